// round 8
// baseline (speedup 1.0000x reference)
#include <cuda_runtime.h>
#include <cuda_bf16.h>
#include <cstdint>

// ============================================================================
// Block-diagonal irrep linear, fused HMMA bf16 3-term split kernel.
// R8: B operand pre-laid-out in mma-fragment order in global (no smem for B),
//     DIM>1 epilogue staged in output order -> float4 coalesced stores.
// ============================================================================

__device__ __forceinline__ uint32_t smem_u32(const void* p) {
    uint32_t a;
    asm("{ .reg .u64 t; cvta.to.shared.u64 t, %1; cvt.u32.u64 %0, t; }" : "=r"(a) : "l"(p));
    return a;
}
__device__ __forceinline__ void ldsm4(uint32_t* r, uint32_t addr) {
    asm volatile("ldmatrix.sync.aligned.m8n8.x4.shared.b16 {%0,%1,%2,%3}, [%4];"
                 : "=r"(r[0]), "=r"(r[1]), "=r"(r[2]), "=r"(r[3]) : "r"(addr));
}
__device__ __forceinline__ void mma16816(float* c, const uint32_t* a, const uint32_t* b) {
    asm volatile("mma.sync.aligned.m16n8k16.row.col.f32.bf16.bf16.f32 "
                 "{%0,%1,%2,%3}, {%4,%5,%6,%7}, {%8,%9}, {%0,%1,%2,%3};"
                 : "+f"(c[0]), "+f"(c[1]), "+f"(c[2]), "+f"(c[3])
                 : "r"(a[0]), "r"(a[1]), "r"(a[2]), "r"(a[3]), "r"(b[0]), "r"(b[1]));
}
__device__ __forceinline__ void split_bf16(float v, __nv_bfloat16& h, __nv_bfloat16& l) {
    h = __float2bfloat16(v);
    l = __float2bfloat16(v - __bfloat162float(h));
}
__device__ __forceinline__ uint32_t pack2(__nv_bfloat16 a, __nv_bfloat16 b) {
    return ((uint32_t)__bfloat16_as_ushort(b) << 16) | __bfloat16_as_ushort(a);
}

// ---- W fragment images: bf16 halves in exact m16n8k16 B-fragment order ----
// index = WOFF + (((c*KS+ks)*(MUL/8) + n8)*32 + lane)*4 + reg*2 + half
// per-lane uint2 = {reg0, reg1} for one n8 fragment. pw pre-folded.
__device__ __align__(16) __nv_bfloat16 g_bfh[21760];
__device__ __align__(16) __nv_bfloat16 g_bfl[21760];

__global__ void w_prep_kernel(const float* __restrict__ w) {
    int t = blockIdx.x * 256 + threadIdx.x;
    if (t >= 21760) return;
    int mul, woff, kc; float pw;
    if (t < 16384)      { mul = 128; woff = 0;     kc = 32; pw = 0.08838834764831845f; }
    else if (t < 20480) { mul = 64;  woff = 16384; kc = 32; pw = 0.125f; }
    else if (t < 21504) { mul = 32;  woff = 20480; kc = 32; pw = 0.17677669529663687f; }
    else                { mul = 16;  woff = 21504; kc = 16; pw = 0.25f; }
    const int local = t - woff;
    const int u = local / mul;          // k index (W is [u][n] row-major)
    const int n = local - u * mul;
    const int c   = u / kc;
    const int kl  = u - c * kc;
    const int ks  = kl >> 4;
    const int k16 = kl & 15;
    const int lane = (n & 7) * 4 + ((k16 & 7) >> 1);
    const int reg  = k16 >> 3;
    const int half = k16 & 1;
    const int KSb  = kc >> 4;
    const int idx = woff +
        ((((c * KSb + ks) * (mul >> 3) + (n >> 3)) * 32 + lane) * 4) + reg * 2 + half;
    float val = w[t] * pw;
    __nv_bfloat16 h, l;
    split_bf16(val, h, l);
    g_bfh[idx] = h;
    g_bfl[idx] = l;
}

// ---- per-block GEMM body ----
template <int MUL, int DIM, int OFF, int WOFF, int WM, int WN, int MITER>
__device__ __forceinline__ void irrep_gemm(
    const float* __restrict__ x, float* __restrict__ out,
    int batch, int cta, char* smem)
{
    constexpr int KC    = (MUL < 32) ? MUL : 32;
    constexpr int NCH   = MUL / KC;
    constexpr int KS    = KC / 16;
    constexpr int PA    = KC + 8;                 // A row stride (halves); conflict-free
    constexpr int NPW   = MUL / WN;
    constexpr int NF    = NPW / 8;
    constexpr int MROWS = WM * MITER * 16;
    constexpr int PD2   = MUL * DIM + 4;          // output-ordered stage stride (floats)

    __nv_bfloat16* Ah = (__nv_bfloat16*)smem;
    __nv_bfloat16* Al = Ah + MROWS * PA;
    float* Dst2 = (float*)smem;                   // epilogue alias (output order)

    const int tid  = threadIdx.x;
    const int lane = tid & 31;
    const int wid  = tid >> 5;
    const int m0   = cta * MROWS;
    const int mw   = (wid & (WM - 1)) * 16;
    const int nw   = (WN == 2) ? (wid >> 2) * NPW : 0;
    const int n80  = nw >> 3;

    const int z_lo = m0 / DIM;
    int z_hi = (m0 + MROWS - 1) / DIM;
    if (z_hi > batch - 1) z_hi = batch - 1;
    const int n_rows = z_hi - z_lo + 1;
    const int mbase  = z_lo * DIM - m0;           // in (-DIM, 0]

    const uint32_t sAh = smem_u32(Ah), sAl = smem_u32(Al);
    uint32_t aoff[MITER];
    #pragma unroll
    for (int mi = 0; mi < MITER; ++mi)
        aoff[mi] = (uint32_t)(((mi * WM * 16 + mw + (lane & 15)) * PA
                               + ((lane >> 4) & 1) * 8) * 2);

    const uint2* __restrict__ fh = (const uint2*)(g_bfh + WOFF);
    const uint2* __restrict__ fl = (const uint2*)(g_bfl + WOFF);

    float acc[MITER][NF][4];
    #pragma unroll
    for (int mi = 0; mi < MITER; ++mi)
        #pragma unroll
        for (int f = 0; f < NF; ++f)
            #pragma unroll
            for (int j = 0; j < 4; ++j) acc[mi][f][j] = 0.0f;

    const int nr = (batch - z_lo < MROWS) ? (batch - z_lo) : MROWS;  // DIM==1
    constexpr int Q = KC / 4;

    float4 pre[2];
    auto load_chunk = [&](int c) {
        const int c0_ = OFF + c * KC;
        #pragma unroll
        for (int t = 0; t < 2; ++t) {
            const int idx = tid + t * 256;
            if (idx < nr * Q)
                pre[t] = *(const float4*)(x + (long)(z_lo + (idx >> 3)) * 592
                                          + c0_ + (idx & 7) * 4);
        }
    };
    auto store_chunk = [&]() {
        #pragma unroll
        for (int t = 0; t < 2; ++t) {
            const int idx = tid + t * 256;
            if (idx < nr * Q) {
                const float4 v = pre[t];
                __nv_bfloat16 h0, l0, h1, l1, h2, l2, h3, l3;
                split_bf16(v.x, h0, l0); split_bf16(v.y, h1, l1);
                split_bf16(v.z, h2, l2); split_bf16(v.w, h3, l3);
                const int r = idx >> 3, q = idx & 7;
                *(uint2*)&Ah[r * PA + q * 4] = make_uint2(pack2(h0, h1), pack2(h2, h3));
                *(uint2*)&Al[r * PA + q * 4] = make_uint2(pack2(l0, l1), pack2(l2, l3));
            }
        }
    };
    auto mma_chunk = [&](int c) {
        #pragma unroll
        for (int ks = 0; ks < KS; ++ks) {
            uint32_t ah[MITER][4], al[MITER][4];
            #pragma unroll
            for (int mi = 0; mi < MITER; ++mi) {
                ldsm4(ah[mi], sAh + aoff[mi] + ks * 32);
                ldsm4(al[mi], sAl + aoff[mi] + ks * 32);
            }
            const int fb = ((c * KS + ks) * (MUL / 8) + n80) * 32 + lane;
            #pragma unroll
            for (int nf = 0; nf < NF; ++nf) {
                const uint2 bh = fh[fb + nf * 32];
                const uint2 bl = fl[fb + nf * 32];
                #pragma unroll
                for (int mi = 0; mi < MITER; ++mi) {
                    mma16816(acc[mi][nf], ah[mi], (const uint32_t*)&bh);
                    mma16816(acc[mi][nf], ah[mi], (const uint32_t*)&bl);
                    mma16816(acc[mi][nf], al[mi], (const uint32_t*)&bh);
                }
            }
        }
    };

    if constexpr (DIM == 1) {
        load_chunk(0);
        for (int c = 0; c < NCH; ++c) {
            __syncthreads();
            store_chunk();
            __syncthreads();
            if (c + 1 < NCH) load_chunk(c + 1);
            mma_chunk(c);
        }
    } else {
        constexpr int KC2 = KC / 2;
        constexpr int ZST = 256 / KC2;
        const int up   = (tid & (KC2 - 1)) * 2;
        const int zoff = tid / KC2;
        for (int c = 0; c < NCH; ++c) {
            if (c) __syncthreads();
            const int c0 = OFF + c * KC * DIM;
            for (int zz = zoff; zz < n_rows; zz += ZST) {
                const float2* bp = (const float2*)(x + (long)(z_lo + zz) * 592
                                                   + c0 + up * DIM);
                float r[2 * DIM];
                #pragma unroll
                for (int t = 0; t < DIM; ++t) {
                    const float2 v = bp[t];
                    r[2 * t] = v.x; r[2 * t + 1] = v.y;
                }
                const int mlb = mbase + zz * DIM;
                #pragma unroll
                for (int i = 0; i < DIM; ++i) {
                    const int ml = mlb + i;
                    if (ml >= 0 && ml < MROWS) {
                        __nv_bfloat16 h0, l0, h1, l1;
                        split_bf16(r[i], h0, l0);
                        split_bf16(r[i + DIM], h1, l1);
                        *(uint32_t*)&Ah[ml * PA + up] = pack2(h0, h1);
                        *(uint32_t*)&Al[ml * PA + up] = pack2(l0, l1);
                    }
                }
            }
            __syncthreads();
            mma_chunk(c);
        }
    }

    // ---- epilogue ----
    if constexpr (DIM == 1) {
        // direct register -> gmem
        const int r0 = mw + (lane >> 2);
        const int nc = (lane & 3) * 2;
        #pragma unroll
        for (int h = 0; h < 2; ++h) {
            const int z = z_lo + r0 + h * 8;
            if (z < batch) {
                float* orow = out + (long)z * 592 + OFF + nw + nc;
                #pragma unroll
                for (int nf = 0; nf < NF; ++nf)
                    *(float2*)(orow + nf * 8) =
                        make_float2(acc[0][nf][2 * h], acc[0][nf][2 * h + 1]);
            }
        }
    } else {
        __syncthreads();   // last mma read Ah; Dst2 aliases it
        // stage in OUTPUT order: Dst2[zz][n*DIM + i]
        {
            const int nc = (lane & 3) * 2;
            #pragma unroll
            for (int mi = 0; mi < MITER; ++mi) {
                #pragma unroll
                for (int h = 0; h < 2; ++h) {
                    const int r = mi * WM * 16 + mw + (lane >> 2) + h * 8;
                    const int t = r - mbase;           // >= 0
                    const int zz = t / DIM;
                    const int i  = t - zz * DIM;
                    float* rowp = &Dst2[zz * PD2 + nc * DIM + i];
                    #pragma unroll
                    for (int nf = 0; nf < NF; ++nf) {
                        rowp[nf * 8 * DIM]       = acc[mi][nf][2 * h];
                        rowp[nf * 8 * DIM + DIM] = acc[mi][nf][2 * h + 1];
                    }
                }
            }
        }
        __syncthreads();
        // copy out: full rows via float4, edge rows guarded scalar
        const int M = batch * DIM;
        const int mmax = (M - m0 < MROWS) ? (M - m0) : MROWS;
        constexpr int W4 = MUL * DIM / 4;
        for (int idx = tid; idx < n_rows * W4; idx += 256) {
            const int zz = idx / W4;
            const int q  = idx - zz * W4;
            const int mlb = mbase + zz * DIM;
            float* op = out + (long)(z_lo + zz) * 592 + OFF + q * 4;
            if (mlb >= 0 && mlb + DIM <= mmax) {
                *(float4*)op = *(const float4*)&Dst2[zz * PD2 + q * 4];
            } else {
                #pragma unroll
                for (int e = 0; e < 4; ++e) {
                    const int cc = q * 4 + e;
                    const int i2 = cc % DIM;
                    const int ml = mlb + i2;
                    if (ml >= 0 && ml < mmax) op[e] = Dst2[zz * PD2 + cc];
                }
            }
        }
    }
}

__global__ void __launch_bounds__(256, 4) fused_irrep_kernel(
    const float* __restrict__ x, float* __restrict__ out, int batch,
    int nb0, int nb01, int nb012)
{
    extern __shared__ char smem[];
    const int b = blockIdx.x;
    if (b < nb0) {
        irrep_gemm<128, 1, 0, 0, 4, 2, 1>(x, out, batch, b, smem);
    } else if (b < nb01) {
        irrep_gemm<64, 3, 128, 16384, 8, 1, 1>(x, out, batch, b - nb0, smem);
    } else if (b < nb012) {
        irrep_gemm<32, 5, 320, 20480, 8, 1, 1>(x, out, batch, b - nb01, smem);
    } else {
        irrep_gemm<16, 7, 480, 21504, 8, 1, 2>(x, out, batch, b - nb012, smem);
    }
}

extern "C" void kernel_launch(void* const* d_in, const int* in_sizes, int n_in,
                              void* d_out, int out_size)
{
    const float* x = (const float*)d_in[0];
    const float* w = (const float*)d_in[1];
    float* out = (float*)d_out;
    const int batch = in_sizes[0] / 592;

    w_prep_kernel<<<(21760 + 255) / 256, 256>>>(w);

    const int nb0 = (batch + 63) / 64;          // MROWS 64
    const int nb1 = (batch * 3 + 127) / 128;    // MROWS 128
    const int nb2 = (batch * 5 + 127) / 128;    // MROWS 128
    const int nb3 = (batch * 7 + 255) / 256;    // MROWS 256
    const int total = nb0 + nb1 + nb2 + nb3;

    // max smem: block1 Dst2 = 44 rows * 196 floats * 4 = 34496 B
    const size_t smem = 34560;
    cudaFuncSetAttribute(fused_irrep_kernel,
                         cudaFuncAttributeMaxDynamicSharedMemorySize, (int)smem);
    fused_irrep_kernel<<<total, 256, smem>>>(x, out, batch,
                                             nb0, nb0 + nb1, nb0 + nb1 + nb2);
}

// round 9
// speedup vs baseline: 1.1227x; 1.1227x over previous
#include <cuda_runtime.h>
#include <cuda_bf16.h>
#include <cstdint>

// ============================================================================
// Block-diagonal irrep linear, fused HMMA bf16 3-term split kernel.
// R9: B back in smem (R7 path); DIM>1 epilogue staged in OUTPUT order ->
//     float4 coalesced stores (replaces strided scalar STG).
// ============================================================================

__device__ __forceinline__ uint32_t smem_u32(const void* p) {
    uint32_t a;
    asm("{ .reg .u64 t; cvta.to.shared.u64 t, %1; cvt.u32.u64 %0, t; }" : "=r"(a) : "l"(p));
    return a;
}
__device__ __forceinline__ void ldsm4(uint32_t* r, uint32_t addr) {
    asm volatile("ldmatrix.sync.aligned.m8n8.x4.shared.b16 {%0,%1,%2,%3}, [%4];"
                 : "=r"(r[0]), "=r"(r[1]), "=r"(r[2]), "=r"(r[3]) : "r"(addr));
}
__device__ __forceinline__ void mma16816(float* c, const uint32_t* a, const uint32_t* b) {
    asm volatile("mma.sync.aligned.m16n8k16.row.col.f32.bf16.bf16.f32 "
                 "{%0,%1,%2,%3}, {%4,%5,%6,%7}, {%8,%9}, {%0,%1,%2,%3};"
                 : "+f"(c[0]), "+f"(c[1]), "+f"(c[2]), "+f"(c[3])
                 : "r"(a[0]), "r"(a[1]), "r"(a[2]), "r"(a[3]), "r"(b[0]), "r"(b[1]));
}
__device__ __forceinline__ void split_bf16(float v, __nv_bfloat16& h, __nv_bfloat16& l) {
    h = __float2bfloat16(v);
    l = __float2bfloat16(v - __bfloat162float(h));
}
__device__ __forceinline__ uint32_t pack2(__nv_bfloat16 a, __nv_bfloat16 b) {
    return ((uint32_t)__bfloat16_as_ushort(b) << 16) | __bfloat16_as_ushort(a);
}

// ---- W images: per block, per K-chunk, [n][kl], padded stride PB=KC+8 ----
// halves offsets: b0=0 (4 x 128x40), b1=20480 (2 x 64x40), b2=25600 (32x40),
// b3=26880 (16x24); total 27264
__device__ __align__(16) __nv_bfloat16 g_bh[27264];
__device__ __align__(16) __nv_bfloat16 g_bl[27264];

__global__ void w_prep_kernel(const float* __restrict__ w) {
    int t = blockIdx.x * 256 + threadIdx.x;
    if (t >= 21760) return;
    int dst; float pw;
    if (t < 16384) {                  // block0: MUL=128, KC=32
        int u = t >> 7, n = t & 127;
        dst = ((u >> 5) * 5120) + n * 40 + (u & 31);
        pw = 0.08838834764831845f;
    } else if (t < 20480) {           // block1: MUL=64, KC=32
        int local = t - 16384;
        int u = local >> 6, n = local & 63;
        dst = 20480 + ((u >> 5) * 2560) + n * 40 + (u & 31);
        pw = 0.125f;
    } else if (t < 21504) {           // block2: MUL=32, KC=32
        int local = t - 20480;
        int u = local >> 5, n = local & 31;
        dst = 25600 + n * 40 + u;
        pw = 0.17677669529663687f;
    } else {                          // block3: MUL=16, KC=16
        int local = t - 21504;
        int u = local >> 4, n = local & 15;
        dst = 26880 + n * 24 + u;
        pw = 0.25f;
    }
    float val = w[t] * pw;
    __nv_bfloat16 h, l;
    split_bf16(val, h, l);
    g_bh[dst] = h;
    g_bl[dst] = l;
}

// ---- per-block GEMM body ----
template <int MUL, int DIM, int OFF, int IMG, int WM, int WN, int MITER>
__device__ __forceinline__ void irrep_gemm(
    const float* __restrict__ x, float* __restrict__ out,
    int batch, int cta, char* smem)
{
    constexpr int KC    = (MUL < 32) ? MUL : 32;
    constexpr int NCH   = MUL / KC;
    constexpr int KS    = KC / 16;
    constexpr int PA    = KC + 8;
    constexpr int PB    = KC + 8;
    constexpr int NPW   = MUL / WN;
    constexpr int NF    = NPW / 8;
    constexpr int MROWS = WM * MITER * 16;
    constexpr int PD2   = MUL * DIM + 4;          // output-ordered stage stride

    __nv_bfloat16* Ah = (__nv_bfloat16*)smem;
    __nv_bfloat16* Al = Ah + MROWS * PA;
    __nv_bfloat16* Bh = Al + MROWS * PA;
    __nv_bfloat16* Bl = Bh + MUL * PB;
    float* Dst2 = (float*)smem;                   // epilogue alias (output order)

    const int tid  = threadIdx.x;
    const int lane = tid & 31;
    const int wid  = tid >> 5;
    const int m0   = cta * MROWS;
    const int mw   = (wid & (WM - 1)) * 16;
    const int nw   = (WN == 2) ? (wid >> 2) * NPW : 0;

    const int z_lo = m0 / DIM;
    int z_hi = (m0 + MROWS - 1) / DIM;
    if (z_hi > batch - 1) z_hi = batch - 1;
    const int n_rows = z_lo <= z_hi ? (z_hi - z_lo + 1) : 0;
    const int mbase  = z_lo * DIM - m0;           // in (-DIM, 0]

    const uint32_t sAh = smem_u32(Ah), sAl = smem_u32(Al);
    const uint32_t sBh = smem_u32(Bh), sBl = smem_u32(Bl);
    uint32_t aoff[MITER];
    #pragma unroll
    for (int mi = 0; mi < MITER; ++mi)
        aoff[mi] = (uint32_t)(((mi * WM * 16 + mw + (lane & 15)) * PA
                               + ((lane >> 4) & 1) * 8) * 2);
    const uint32_t boff = (uint32_t)(((nw + (lane & 7) + ((lane >> 4) & 1) * 8) * PB
                                      + ((lane >> 3) & 1) * 8) * 2);

    float acc[MITER][NF][4];
    #pragma unroll
    for (int mi = 0; mi < MITER; ++mi)
        #pragma unroll
        for (int f = 0; f < NF; ++f)
            #pragma unroll
            for (int j = 0; j < 4; ++j) acc[mi][f][j] = 0.0f;

    const int nr = (batch - z_lo < MROWS) ? (batch - z_lo) : MROWS;  // DIM==1 rows
    constexpr int Q = KC / 4;                                        // float4/row

    float4 pre[2];
    auto load_chunk = [&](int c) {
        const int c0_ = OFF + c * KC;
        #pragma unroll
        for (int t = 0; t < 2; ++t) {
            const int idx = tid + t * 256;
            if (idx < nr * Q)
                pre[t] = *(const float4*)(x + (long)(z_lo + (idx >> 3)) * 592
                                          + c0_ + (idx & 7) * 4);
        }
    };
    auto store_chunk = [&]() {
        #pragma unroll
        for (int t = 0; t < 2; ++t) {
            const int idx = tid + t * 256;
            if (idx < nr * Q) {
                const float4 v = pre[t];
                __nv_bfloat16 h0, l0, h1, l1, h2, l2, h3, l3;
                split_bf16(v.x, h0, l0); split_bf16(v.y, h1, l1);
                split_bf16(v.z, h2, l2); split_bf16(v.w, h3, l3);
                const int r = idx >> 3, q = idx & 7;
                *(uint2*)&Ah[r * PA + q * 4] = make_uint2(pack2(h0, h1), pack2(h2, h3));
                *(uint2*)&Al[r * PA + q * 4] = make_uint2(pack2(l0, l1), pack2(l2, l3));
            }
        }
    };
    auto copy_b = [&](int c) {
        const uint4* gh = (const uint4*)(g_bh + IMG + c * MUL * PB);
        const uint4* gl = (const uint4*)(g_bl + IMG + c * MUL * PB);
        uint4* dh = (uint4*)Bh;
        uint4* dl = (uint4*)Bl;
        constexpr int CNT = MUL * PB / 8;
        #pragma unroll 2
        for (int i = tid; i < CNT; i += 256) { dh[i] = gh[i]; dl[i] = gl[i]; }
    };
    auto mma_chunk = [&]() {
        #pragma unroll
        for (int ks = 0; ks < KS; ++ks) {
            uint32_t ah[MITER][4], al[MITER][4];
            #pragma unroll
            for (int mi = 0; mi < MITER; ++mi) {
                ldsm4(ah[mi], sAh + aoff[mi] + ks * 32);
                ldsm4(al[mi], sAl + aoff[mi] + ks * 32);
            }
            #pragma unroll
            for (int nf2 = 0; nf2 < NF / 2; ++nf2) {
                uint32_t bh[4], bl[4];
                const uint32_t bo = boff + (uint32_t)(nf2 * 16 * PB * 2) + ks * 32;
                ldsm4(bh, sBh + bo);
                ldsm4(bl, sBl + bo);
                #pragma unroll
                for (int mi = 0; mi < MITER; ++mi) {
                    mma16816(acc[mi][2 * nf2],     ah[mi], bh);
                    mma16816(acc[mi][2 * nf2 + 1], ah[mi], bh + 2);
                    mma16816(acc[mi][2 * nf2],     ah[mi], bl);
                    mma16816(acc[mi][2 * nf2 + 1], ah[mi], bl + 2);
                    mma16816(acc[mi][2 * nf2],     al[mi], bh);
                    mma16816(acc[mi][2 * nf2 + 1], al[mi], bh + 2);
                }
            }
        }
    };

    if constexpr (DIM == 1) {
        load_chunk(0);
        for (int c = 0; c < NCH; ++c) {
            __syncthreads();
            copy_b(c);
            store_chunk();
            __syncthreads();
            if (c + 1 < NCH) load_chunk(c + 1);
            mma_chunk();
        }
    } else {
        constexpr int KC2 = KC / 2;
        constexpr int ZST = 256 / KC2;
        const int up   = (tid & (KC2 - 1)) * 2;
        const int zoff = tid / KC2;
        for (int c = 0; c < NCH; ++c) {
            if (c) __syncthreads();
            copy_b(c);
            const int c0 = OFF + c * KC * DIM;
            for (int zz = zoff; zz < n_rows; zz += ZST) {
                const float2* bp = (const float2*)(x + (long)(z_lo + zz) * 592
                                                   + c0 + up * DIM);
                float r[2 * DIM];
                #pragma unroll
                for (int t = 0; t < DIM; ++t) {
                    const float2 v = bp[t];
                    r[2 * t] = v.x; r[2 * t + 1] = v.y;
                }
                const int mlb = mbase + zz * DIM;
                #pragma unroll
                for (int i = 0; i < DIM; ++i) {
                    const int ml = mlb + i;
                    if (ml >= 0 && ml < MROWS) {
                        __nv_bfloat16 h0, l0, h1, l1;
                        split_bf16(r[i], h0, l0);
                        split_bf16(r[i + DIM], h1, l1);
                        *(uint32_t*)&Ah[ml * PA + up] = pack2(h0, h1);
                        *(uint32_t*)&Al[ml * PA + up] = pack2(l0, l1);
                    }
                }
            }
            __syncthreads();
            mma_chunk();
        }
    }

    // ---- epilogue ----
    if constexpr (DIM == 1) {
        // direct register -> gmem (rows are batch indices; cols 32B-aligned)
        const int r0 = mw + (lane >> 2);
        const int nc = (lane & 3) * 2;
        #pragma unroll
        for (int h = 0; h < 2; ++h) {
            const int z = z_lo + r0 + h * 8;
            if (z < batch) {
                float* orow = out + (long)z * 592 + OFF + nw + nc;
                #pragma unroll
                for (int nf = 0; nf < NF; ++nf)
                    *(float2*)(orow + nf * 8) =
                        make_float2(acc[0][nf][2 * h], acc[0][nf][2 * h + 1]);
            }
        }
    } else {
        __syncthreads();   // last mma read Ah/Bh; Dst2 aliases them
        // stage in OUTPUT order: Dst2[zz][n*DIM + i]  (nw == 0 for DIM>1 blocks)
        {
            const int nc = (lane & 3) * 2;
            #pragma unroll
            for (int mi = 0; mi < MITER; ++mi) {
                #pragma unroll
                for (int h = 0; h < 2; ++h) {
                    const int r = mi * WM * 16 + mw + (lane >> 2) + h * 8;
                    const int t = r - mbase;           // >= 0
                    const int zz = t / DIM;
                    const int i  = t - zz * DIM;
                    float* rowp = &Dst2[zz * PD2 + nc * DIM + i];
                    #pragma unroll
                    for (int nf = 0; nf < NF; ++nf) {
                        rowp[nf * 8 * DIM]       = acc[mi][nf][2 * h];
                        rowp[nf * 8 * DIM + DIM] = acc[mi][nf][2 * h + 1];
                    }
                }
            }
        }
        __syncthreads();
        // copy out: full rows via float4, edge rows guarded scalar
        const int M = batch * DIM;
        const int mmax = (M - m0 < MROWS) ? (M - m0) : MROWS;
        constexpr int W4 = MUL * DIM / 4;
        for (int idx = tid; idx < n_rows * W4; idx += 256) {
            const int zz = idx / W4;
            const int q  = idx - zz * W4;
            const int mlb = mbase + zz * DIM;
            float* op = out + (long)(z_lo + zz) * 592 + OFF + q * 4;
            if (mlb >= 0 && mlb + DIM <= mmax) {
                *(float4*)op = *(const float4*)&Dst2[zz * PD2 + q * 4];
            } else {
                #pragma unroll
                for (int e = 0; e < 4; ++e) {
                    const int cc = q * 4 + e;
                    const int i2 = cc % DIM;
                    const int ml = mlb + i2;
                    if (ml >= 0 && ml < mmax) op[e] = Dst2[zz * PD2 + cc];
                }
            }
        }
    }
}

__global__ void __launch_bounds__(256, 4) fused_irrep_kernel(
    const float* __restrict__ x, float* __restrict__ out, int batch,
    int nb0, int nb01, int nb012)
{
    extern __shared__ char smem[];
    const int b = blockIdx.x;
    if (b < nb0) {
        irrep_gemm<128, 1, 0, 0, 4, 2, 1>(x, out, batch, b, smem);
    } else if (b < nb01) {
        irrep_gemm<64, 3, 128, 20480, 8, 1, 1>(x, out, batch, b - nb0, smem);
    } else if (b < nb012) {
        irrep_gemm<32, 5, 320, 25600, 8, 1, 1>(x, out, batch, b - nb01, smem);
    } else {
        irrep_gemm<16, 7, 480, 26880, 8, 1, 2>(x, out, batch, b - nb012, smem);
    }
}

extern "C" void kernel_launch(void* const* d_in, const int* in_sizes, int n_in,
                              void* d_out, int out_size)
{
    const float* x = (const float*)d_in[0];
    const float* w = (const float*)d_in[1];
    float* out = (float*)d_out;
    const int batch = in_sizes[0] / 592;

    w_prep_kernel<<<(21760 + 255) / 256, 256>>>(w);

    const int nb0 = (batch + 63) / 64;          // MROWS 64
    const int nb1 = (batch * 3 + 127) / 128;    // MROWS 128
    const int nb2 = (batch * 5 + 127) / 128;    // MROWS 128
    const int nb3 = (batch * 7 + 255) / 256;    // MROWS 256
    const int total = nb0 + nb1 + nb2 + nb3;

    // max smem: block1 Dst2 = 44 rows * 196 floats * 4B = 34496
    const size_t smem = 34560;
    cudaFuncSetAttribute(fused_irrep_kernel,
                         cudaFuncAttributeMaxDynamicSharedMemorySize, (int)smem);
    fused_irrep_kernel<<<total, 256, smem>>>(x, out, batch,
                                             nb0, nb0 + nb1, nb0 + nb1 + nb2);
}

// round 12
// speedup vs baseline: 1.2601x; 1.1224x over previous
#include <cuda_runtime.h>
#include <cuda_fp16.h>
#include <cstdint>

// ============================================================================
// Block-diagonal irrep linear, fused HMMA kernel.
// R10: fp16 2-term split: out = (Ah + Al) * Bh, all fp16 (f32 accum).
//      B has NO lo term -> B copy + B ldsm traffic halved, MMA count 2/3.
//      Error ~2.8e-4 rms (B single-rounded fp16), threshold 1e-3.
// ============================================================================

__device__ __forceinline__ uint32_t smem_u32(const void* p) {
    uint32_t a;
    asm("{ .reg .u64 t; cvta.to.shared.u64 t, %1; cvt.u32.u64 %0, t; }" : "=r"(a) : "l"(p));
    return a;
}
__device__ __forceinline__ void ldsm4(uint32_t* r, uint32_t addr) {
    asm volatile("ldmatrix.sync.aligned.m8n8.x4.shared.b16 {%0,%1,%2,%3}, [%4];"
                 : "=r"(r[0]), "=r"(r[1]), "=r"(r[2]), "=r"(r[3]) : "r"(addr));
}
__device__ __forceinline__ void mma16816(float* c, const uint32_t* a, const uint32_t* b) {
    asm volatile("mma.sync.aligned.m16n8k16.row.col.f32.f16.f16.f32 "
                 "{%0,%1,%2,%3}, {%4,%5,%6,%7}, {%8,%9}, {%0,%1,%2,%3};"
                 : "+f"(c[0]), "+f"(c[1]), "+f"(c[2]), "+f"(c[3])
                 : "r"(a[0]), "r"(a[1]), "r"(a[2]), "r"(a[3]), "r"(b[0]), "r"(b[1]));
}
__device__ __forceinline__ void split_fp16(float v, __half& h, __half& l) {
    h = __float2half_rn(v);
    l = __float2half_rn(v - __half2float(h));
}
__device__ __forceinline__ uint32_t pack2h(__half a, __half b) {
    return ((uint32_t)__half_as_ushort(b) << 16) | __half_as_ushort(a);
}

// ---- W image (fp16 hi only): per block, per K-chunk, [n][kl], stride PB=KC+8 ----
// halves offsets: b0=0 (4 x 128x40), b1=20480 (2 x 64x40), b2=25600 (32x40),
// b3=26880 (16x24); total 27264
__device__ __align__(16) __half g_bh[27264];

__global__ void w_prep_kernel(const float* __restrict__ w) {
    int t = blockIdx.x * 256 + threadIdx.x;
    if (t >= 21760) return;
    int dst; float pw;
    if (t < 16384) {                  // block0: MUL=128, KC=32
        int u = t >> 7, n = t & 127;
        dst = ((u >> 5) * 5120) + n * 40 + (u & 31);
        pw = 0.08838834764831845f;
    } else if (t < 20480) {           // block1: MUL=64, KC=32
        int local = t - 16384;
        int u = local >> 6, n = local & 63;
        dst = 20480 + ((u >> 5) * 2560) + n * 40 + (u & 31);
        pw = 0.125f;
    } else if (t < 21504) {           // block2: MUL=32, KC=32
        int local = t - 20480;
        int u = local >> 5, n = local & 31;
        dst = 25600 + n * 40 + u;
        pw = 0.17677669529663687f;
    } else {                          // block3: MUL=16, KC=16
        int local = t - 21504;
        int u = local >> 4, n = local & 15;
        dst = 26880 + n * 24 + u;
        pw = 0.25f;
    }
    g_bh[dst] = __float2half_rn(w[t] * pw);
}

// ---- per-block GEMM body ----
template <int MUL, int DIM, int OFF, int IMG, int WM, int WN, int MITER>
__device__ __forceinline__ void irrep_gemm(
    const float* __restrict__ x, float* __restrict__ out,
    int batch, int cta, char* smem)
{
    constexpr int KC    = (MUL < 32) ? MUL : 32;
    constexpr int NCH   = MUL / KC;
    constexpr int KS    = KC / 16;
    constexpr int PA    = KC + 8;
    constexpr int PB    = KC + 8;
    constexpr int NPW   = MUL / WN;
    constexpr int NF    = NPW / 8;
    constexpr int MROWS = WM * MITER * 16;
    constexpr int PD2   = MUL * DIM + 4;          // output-ordered stage stride

    __half* Ah = (__half*)smem;
    __half* Al = Ah + MROWS * PA;
    __half* Bh = Al + MROWS * PA;
    float* Dst2 = (float*)smem;                   // epilogue alias (output order)

    const int tid  = threadIdx.x;
    const int lane = tid & 31;
    const int wid  = tid >> 5;
    const int m0   = cta * MROWS;
    const int mw   = (wid & (WM - 1)) * 16;
    const int nw   = (WN == 2) ? (wid >> 2) * NPW : 0;

    const int z_lo = m0 / DIM;
    int z_hi = (m0 + MROWS - 1) / DIM;
    if (z_hi > batch - 1) z_hi = batch - 1;
    const int n_rows = z_lo <= z_hi ? (z_hi - z_lo + 1) : 0;
    const int mbase  = z_lo * DIM - m0;           // in (-DIM, 0]

    const uint32_t sAh = smem_u32(Ah), sAl = smem_u32(Al);
    const uint32_t sBh = smem_u32(Bh);
    uint32_t aoff[MITER];
    #pragma unroll
    for (int mi = 0; mi < MITER; ++mi)
        aoff[mi] = (uint32_t)(((mi * WM * 16 + mw + (lane & 15)) * PA
                               + ((lane >> 4) & 1) * 8) * 2);
    const uint32_t boff = (uint32_t)(((nw + (lane & 7) + ((lane >> 4) & 1) * 8) * PB
                                      + ((lane >> 3) & 1) * 8) * 2);

    float acc[MITER][NF][4];
    #pragma unroll
    for (int mi = 0; mi < MITER; ++mi)
        #pragma unroll
        for (int f = 0; f < NF; ++f)
            #pragma unroll
            for (int j = 0; j < 4; ++j) acc[mi][f][j] = 0.0f;

    const int nr = (batch - z_lo < MROWS) ? (batch - z_lo) : MROWS;  // DIM==1 rows
    constexpr int Q = KC / 4;                                        // float4/row

    float4 pre[2];
    auto load_chunk = [&](int c) {
        const int c0_ = OFF + c * KC;
        #pragma unroll
        for (int t = 0; t < 2; ++t) {
            const int idx = tid + t * 256;
            if (idx < nr * Q)
                pre[t] = *(const float4*)(x + (long)(z_lo + (idx >> 3)) * 592
                                          + c0_ + (idx & 7) * 4);
        }
    };
    auto store_chunk = [&]() {
        #pragma unroll
        for (int t = 0; t < 2; ++t) {
            const int idx = tid + t * 256;
            if (idx < nr * Q) {
                const float4 v = pre[t];
                __half h0, l0, h1, l1, h2, l2, h3, l3;
                split_fp16(v.x, h0, l0); split_fp16(v.y, h1, l1);
                split_fp16(v.z, h2, l2); split_fp16(v.w, h3, l3);
                const int r = idx >> 3, q = idx & 7;
                *(uint2*)&Ah[r * PA + q * 4] = make_uint2(pack2h(h0, h1), pack2h(h2, h3));
                *(uint2*)&Al[r * PA + q * 4] = make_uint2(pack2h(l0, l1), pack2h(l2, l3));
            }
        }
    };
    auto copy_b = [&](int c) {
        const uint4* gh = (const uint4*)(g_bh + IMG + c * MUL * PB);
        uint4* dh = (uint4*)Bh;
        constexpr int CNT = MUL * PB / 8;
        #pragma unroll 2
        for (int i = tid; i < CNT; i += 256) dh[i] = gh[i];
    };
    auto mma_chunk = [&]() {
        #pragma unroll
        for (int ks = 0; ks < KS; ++ks) {
            uint32_t ah[MITER][4], al[MITER][4];
            #pragma unroll
            for (int mi = 0; mi < MITER; ++mi) {
                ldsm4(ah[mi], sAh + aoff[mi] + ks * 32);
                ldsm4(al[mi], sAl + aoff[mi] + ks * 32);
            }
            #pragma unroll
            for (int nf2 = 0; nf2 < NF / 2; ++nf2) {
                uint32_t bh[4];
                const uint32_t bo = boff + (uint32_t)(nf2 * 16 * PB * 2) + ks * 32;
                ldsm4(bh, sBh + bo);
                #pragma unroll
                for (int mi = 0; mi < MITER; ++mi) {
                    mma16816(acc[mi][2 * nf2],     ah[mi], bh);
                    mma16816(acc[mi][2 * nf2 + 1], ah[mi], bh + 2);
                    mma16816(acc[mi][2 * nf2],     al[mi], bh);
                    mma16816(acc[mi][2 * nf2 + 1], al[mi], bh + 2);
                }
            }
        }
    };

    if constexpr (DIM == 1) {
        load_chunk(0);
        for (int c = 0; c < NCH; ++c) {
            __syncthreads();
            copy_b(c);
            store_chunk();
            __syncthreads();
            if (c + 1 < NCH) load_chunk(c + 1);
            mma_chunk();
        }
    } else {
        constexpr int KC2 = KC / 2;
        constexpr int ZST = 256 / KC2;
        const int up   = (tid & (KC2 - 1)) * 2;
        const int zoff = tid / KC2;
        for (int c = 0; c < NCH; ++c) {
            if (c) __syncthreads();
            copy_b(c);
            const int c0 = OFF + c * KC * DIM;
            for (int zz = zoff; zz < n_rows; zz += ZST) {
                const float2* bp = (const float2*)(x + (long)(z_lo + zz) * 592
                                                   + c0 + up * DIM);
                float r[2 * DIM];
                #pragma unroll
                for (int t = 0; t < DIM; ++t) {
                    const float2 v = bp[t];
                    r[2 * t] = v.x; r[2 * t + 1] = v.y;
                }
                const int mlb = mbase + zz * DIM;
                #pragma unroll
                for (int i = 0; i < DIM; ++i) {
                    const int ml = mlb + i;
                    if (ml >= 0 && ml < MROWS) {
                        __half h0, l0, h1, l1;
                        split_fp16(r[i], h0, l0);
                        split_fp16(r[i + DIM], h1, l1);
                        *(uint32_t*)&Ah[ml * PA + up] = pack2h(h0, h1);
                        *(uint32_t*)&Al[ml * PA + up] = pack2h(l0, l1);
                    }
                }
            }
            __syncthreads();
            mma_chunk();
        }
    }

    // ---- epilogue ----
    if constexpr (DIM == 1) {
        // direct register -> gmem (rows are batch indices; cols 32B-aligned)
        const int r0 = mw + (lane >> 2);
        const int nc = (lane & 3) * 2;
        #pragma unroll
        for (int h = 0; h < 2; ++h) {
            const int z = z_lo + r0 + h * 8;
            if (z < batch) {
                float* orow = out + (long)z * 592 + OFF + nw + nc;
                #pragma unroll
                for (int nf = 0; nf < NF; ++nf)
                    *(float2*)(orow + nf * 8) =
                        make_float2(acc[0][nf][2 * h], acc[0][nf][2 * h + 1]);
            }
        }
    } else {
        __syncthreads();   // last mma read Ah/Bh; Dst2 aliases them
        // stage in OUTPUT order: Dst2[zz][n*DIM + i]  (nw == 0 for DIM>1 blocks)
        {
            const int nc = (lane & 3) * 2;
            #pragma unroll
            for (int mi = 0; mi < MITER; ++mi) {
                #pragma unroll
                for (int h = 0; h < 2; ++h) {
                    const int r = mi * WM * 16 + mw + (lane >> 2) + h * 8;
                    const int t = r - mbase;           // >= 0
                    const int zz = t / DIM;
                    const int i  = t - zz * DIM;
                    float* rowp = &Dst2[zz * PD2 + nc * DIM + i];
                    #pragma unroll
                    for (int nf = 0; nf < NF; ++nf) {
                        rowp[nf * 8 * DIM]       = acc[mi][nf][2 * h];
                        rowp[nf * 8 * DIM + DIM] = acc[mi][nf][2 * h + 1];
                    }
                }
            }
        }
        __syncthreads();
        // copy out: full rows via float4, edge rows guarded scalar
        const int M = batch * DIM;
        const int mmax = (M - m0 < MROWS) ? (M - m0) : MROWS;
        constexpr int W4 = MUL * DIM / 4;
        for (int idx = tid; idx < n_rows * W4; idx += 256) {
            const int zz = idx / W4;
            const int q  = idx - zz * W4;
            const int mlb = mbase + zz * DIM;
            float* op = out + (long)(z_lo + zz) * 592 + OFF + q * 4;
            if (mlb >= 0 && mlb + DIM <= mmax) {
                *(float4*)op = *(const float4*)&Dst2[zz * PD2 + q * 4];
            } else {
                #pragma unroll
                for (int e = 0; e < 4; ++e) {
                    const int cc = q * 4 + e;
                    const int i2 = cc % DIM;
                    const int ml = mlb + i2;
                    if (ml >= 0 && ml < mmax) op[e] = Dst2[zz * PD2 + cc];
                }
            }
        }
    }
}

__global__ void __launch_bounds__(256, 4) fused_irrep_kernel(
    const float* __restrict__ x, float* __restrict__ out, int batch,
    int nb0, int nb01, int nb012)
{
    extern __shared__ char smem[];
    const int b = blockIdx.x;
    if (b < nb0) {
        irrep_gemm<128, 1, 0, 0, 4, 2, 1>(x, out, batch, b, smem);
    } else if (b < nb01) {
        irrep_gemm<64, 3, 128, 20480, 8, 1, 1>(x, out, batch, b - nb0, smem);
    } else if (b < nb012) {
        irrep_gemm<32, 5, 320, 25600, 8, 1, 1>(x, out, batch, b - nb01, smem);
    } else {
        irrep_gemm<16, 7, 480, 26880, 8, 1, 2>(x, out, batch, b - nb012, smem);
    }
}

extern "C" void kernel_launch(void* const* d_in, const int* in_sizes, int n_in,
                              void* d_out, int out_size)
{
    const float* x = (const float*)d_in[0];
    const float* w = (const float*)d_in[1];
    float* out = (float*)d_out;
    const int batch = in_sizes[0] / 592;

    w_prep_kernel<<<(21760 + 255) / 256, 256>>>(w);

    const int nb0 = (batch + 63) / 64;          // MROWS 64
    const int nb1 = (batch * 3 + 127) / 128;    // MROWS 128
    const int nb2 = (batch * 5 + 127) / 128;    // MROWS 128
    const int nb3 = (batch * 7 + 255) / 256;    // MROWS 256
    const int total = nb0 + nb1 + nb2 + nb3;

    // max smem: block1 Dst2 = 44 rows * 196 floats * 4B = 34496
    const size_t smem = 34560;
    cudaFuncSetAttribute(fused_irrep_kernel,
                         cudaFuncAttributeMaxDynamicSharedMemorySize, (int)smem);
    fused_irrep_kernel<<<total, 256, smem>>>(x, out, batch,
                                             nb0, nb0 + nb1, nb0 + nb1 + nb2);
}

// round 13
// speedup vs baseline: 1.4582x; 1.1572x over previous
#include <cuda_runtime.h>
#include <cuda_fp16.h>
#include <cstdint>

// ============================================================================
// Block-diagonal irrep linear, fused HMMA kernel.
// R13: pure fp16 GEMM: out = Ah * Bh (both single-rounded fp16, f32 accum).
//      Single MMA pass; A lo-term dropped (error budget: ~3e-4 vs 1e-3).
// ============================================================================

__device__ __forceinline__ uint32_t smem_u32(const void* p) {
    uint32_t a;
    asm("{ .reg .u64 t; cvta.to.shared.u64 t, %1; cvt.u32.u64 %0, t; }" : "=r"(a) : "l"(p));
    return a;
}
__device__ __forceinline__ void ldsm4(uint32_t* r, uint32_t addr) {
    asm volatile("ldmatrix.sync.aligned.m8n8.x4.shared.b16 {%0,%1,%2,%3}, [%4];"
                 : "=r"(r[0]), "=r"(r[1]), "=r"(r[2]), "=r"(r[3]) : "r"(addr));
}
__device__ __forceinline__ void mma16816(float* c, const uint32_t* a, const uint32_t* b) {
    asm volatile("mma.sync.aligned.m16n8k16.row.col.f32.f16.f16.f32 "
                 "{%0,%1,%2,%3}, {%4,%5,%6,%7}, {%8,%9}, {%0,%1,%2,%3};"
                 : "+f"(c[0]), "+f"(c[1]), "+f"(c[2]), "+f"(c[3])
                 : "r"(a[0]), "r"(a[1]), "r"(a[2]), "r"(a[3]), "r"(b[0]), "r"(b[1]));
}
__device__ __forceinline__ uint32_t pack2h(__half a, __half b) {
    return ((uint32_t)__half_as_ushort(b) << 16) | __half_as_ushort(a);
}

// ---- W image (fp16): per block, per K-chunk, [n][kl], stride PB=KC+8 ----
// offsets: b0=0 (4 x 128x40), b1=20480 (2 x 64x40), b2=25600 (32x40),
// b3=26880 (16x24); total 27264
__device__ __align__(16) __half g_bh[27264];

__global__ void w_prep_kernel(const float* __restrict__ w) {
    int t = blockIdx.x * 256 + threadIdx.x;
    if (t >= 21760) return;
    int dst; float pw;
    if (t < 16384) {                  // block0: MUL=128, KC=32
        int u = t >> 7, n = t & 127;
        dst = ((u >> 5) * 5120) + n * 40 + (u & 31);
        pw = 0.08838834764831845f;
    } else if (t < 20480) {           // block1: MUL=64, KC=32
        int local = t - 16384;
        int u = local >> 6, n = local & 63;
        dst = 20480 + ((u >> 5) * 2560) + n * 40 + (u & 31);
        pw = 0.125f;
    } else if (t < 21504) {           // block2: MUL=32, KC=32
        int local = t - 20480;
        int u = local >> 5, n = local & 31;
        dst = 25600 + n * 40 + u;
        pw = 0.17677669529663687f;
    } else {                          // block3: MUL=16, KC=16
        int local = t - 21504;
        int u = local >> 4, n = local & 15;
        dst = 26880 + n * 24 + u;
        pw = 0.25f;
    }
    g_bh[dst] = __float2half_rn(w[t] * pw);
}

// ---- per-block GEMM body ----
template <int MUL, int DIM, int OFF, int IMG, int WM, int WN, int MITER>
__device__ __forceinline__ void irrep_gemm(
    const float* __restrict__ x, float* __restrict__ out,
    int batch, int cta, char* smem)
{
    constexpr int KC    = (MUL < 32) ? MUL : 32;
    constexpr int NCH   = MUL / KC;
    constexpr int KS    = KC / 16;
    constexpr int PA    = KC + 8;
    constexpr int PB    = KC + 8;
    constexpr int NPW   = MUL / WN;
    constexpr int NF    = NPW / 8;
    constexpr int MROWS = WM * MITER * 16;
    constexpr int PD2   = MUL * DIM + 4;          // output-ordered stage stride

    __half* Ah = (__half*)smem;
    __half* Bh = Ah + MROWS * PA;
    float* Dst2 = (float*)smem;                   // epilogue alias (output order)

    const int tid  = threadIdx.x;
    const int lane = tid & 31;
    const int wid  = tid >> 5;
    const int m0   = cta * MROWS;
    const int mw   = (wid & (WM - 1)) * 16;
    const int nw   = (WN == 2) ? (wid >> 2) * NPW : 0;

    const int z_lo = m0 / DIM;
    int z_hi = (m0 + MROWS - 1) / DIM;
    if (z_hi > batch - 1) z_hi = batch - 1;
    const int n_rows = z_lo <= z_hi ? (z_hi - z_lo + 1) : 0;
    const int mbase  = z_lo * DIM - m0;           // in (-DIM, 0]

    const uint32_t sAh = smem_u32(Ah);
    const uint32_t sBh = smem_u32(Bh);
    uint32_t aoff[MITER];
    #pragma unroll
    for (int mi = 0; mi < MITER; ++mi)
        aoff[mi] = (uint32_t)(((mi * WM * 16 + mw + (lane & 15)) * PA
                               + ((lane >> 4) & 1) * 8) * 2);
    const uint32_t boff = (uint32_t)(((nw + (lane & 7) + ((lane >> 4) & 1) * 8) * PB
                                      + ((lane >> 3) & 1) * 8) * 2);

    float acc[MITER][NF][4];
    #pragma unroll
    for (int mi = 0; mi < MITER; ++mi)
        #pragma unroll
        for (int f = 0; f < NF; ++f)
            #pragma unroll
            for (int j = 0; j < 4; ++j) acc[mi][f][j] = 0.0f;

    const int nr = (batch - z_lo < MROWS) ? (batch - z_lo) : MROWS;  // DIM==1 rows
    constexpr int Q = KC / 4;                                        // float4/row

    float4 pre[2];
    auto load_chunk = [&](int c) {
        const int c0_ = OFF + c * KC;
        #pragma unroll
        for (int t = 0; t < 2; ++t) {
            const int idx = tid + t * 256;
            if (idx < nr * Q)
                pre[t] = *(const float4*)(x + (long)(z_lo + (idx >> 3)) * 592
                                          + c0_ + (idx & 7) * 4);
        }
    };
    auto store_chunk = [&]() {
        #pragma unroll
        for (int t = 0; t < 2; ++t) {
            const int idx = tid + t * 256;
            if (idx < nr * Q) {
                const float4 v = pre[t];
                const int r = idx >> 3, q = idx & 7;
                *(uint2*)&Ah[r * PA + q * 4] = make_uint2(
                    pack2h(__float2half_rn(v.x), __float2half_rn(v.y)),
                    pack2h(__float2half_rn(v.z), __float2half_rn(v.w)));
            }
        }
    };
    auto copy_b = [&](int c) {
        const uint4* gh = (const uint4*)(g_bh + IMG + c * MUL * PB);
        uint4* dh = (uint4*)Bh;
        constexpr int CNT = MUL * PB / 8;
        #pragma unroll 2
        for (int i = tid; i < CNT; i += 256) dh[i] = gh[i];
    };
    auto mma_chunk = [&]() {
        #pragma unroll
        for (int ks = 0; ks < KS; ++ks) {
            uint32_t ah[MITER][4];
            #pragma unroll
            for (int mi = 0; mi < MITER; ++mi)
                ldsm4(ah[mi], sAh + aoff[mi] + ks * 32);
            #pragma unroll
            for (int nf2 = 0; nf2 < NF / 2; ++nf2) {
                uint32_t bh[4];
                const uint32_t bo = boff + (uint32_t)(nf2 * 16 * PB * 2) + ks * 32;
                ldsm4(bh, sBh + bo);
                #pragma unroll
                for (int mi = 0; mi < MITER; ++mi) {
                    mma16816(acc[mi][2 * nf2],     ah[mi], bh);
                    mma16816(acc[mi][2 * nf2 + 1], ah[mi], bh + 2);
                }
            }
        }
    };

    if constexpr (DIM == 1) {
        load_chunk(0);
        for (int c = 0; c < NCH; ++c) {
            __syncthreads();
            copy_b(c);
            store_chunk();
            __syncthreads();
            if (c + 1 < NCH) load_chunk(c + 1);
            mma_chunk();
        }
    } else {
        constexpr int KC2 = KC / 2;
        constexpr int ZST = 256 / KC2;
        const int up   = (tid & (KC2 - 1)) * 2;
        const int zoff = tid / KC2;
        for (int c = 0; c < NCH; ++c) {
            if (c) __syncthreads();
            copy_b(c);
            const int c0 = OFF + c * KC * DIM;
            for (int zz = zoff; zz < n_rows; zz += ZST) {
                const float2* bp = (const float2*)(x + (long)(z_lo + zz) * 592
                                                   + c0 + up * DIM);
                float r[2 * DIM];
                #pragma unroll
                for (int t = 0; t < DIM; ++t) {
                    const float2 v = bp[t];
                    r[2 * t] = v.x; r[2 * t + 1] = v.y;
                }
                const int mlb = mbase + zz * DIM;
                #pragma unroll
                for (int i = 0; i < DIM; ++i) {
                    const int ml = mlb + i;
                    if (ml >= 0 && ml < MROWS)
                        *(uint32_t*)&Ah[ml * PA + up] =
                            pack2h(__float2half_rn(r[i]), __float2half_rn(r[i + DIM]));
                }
            }
            __syncthreads();
            mma_chunk();
        }
    }

    // ---- epilogue ----
    if constexpr (DIM == 1) {
        // direct register -> gmem (rows are batch indices; cols 32B-aligned)
        const int r0 = mw + (lane >> 2);
        const int nc = (lane & 3) * 2;
        #pragma unroll
        for (int h = 0; h < 2; ++h) {
            const int z = z_lo + r0 + h * 8;
            if (z < batch) {
                float* orow = out + (long)z * 592 + OFF + nw + nc;
                #pragma unroll
                for (int nf = 0; nf < NF; ++nf)
                    *(float2*)(orow + nf * 8) =
                        make_float2(acc[0][nf][2 * h], acc[0][nf][2 * h + 1]);
            }
        }
    } else {
        __syncthreads();   // last mma read Ah/Bh; Dst2 aliases them
        // stage in OUTPUT order: Dst2[zz][n*DIM + i]  (nw == 0 for DIM>1 blocks)
        {
            const int nc = (lane & 3) * 2;
            #pragma unroll
            for (int mi = 0; mi < MITER; ++mi) {
                #pragma unroll
                for (int h = 0; h < 2; ++h) {
                    const int r = mi * WM * 16 + mw + (lane >> 2) + h * 8;
                    const int t = r - mbase;           // >= 0
                    const int zz = t / DIM;
                    const int i  = t - zz * DIM;
                    float* rowp = &Dst2[zz * PD2 + nc * DIM + i];
                    #pragma unroll
                    for (int nf = 0; nf < NF; ++nf) {
                        rowp[nf * 8 * DIM]       = acc[mi][nf][2 * h];
                        rowp[nf * 8 * DIM + DIM] = acc[mi][nf][2 * h + 1];
                    }
                }
            }
        }
        __syncthreads();
        // copy out: full rows via float4, edge rows guarded scalar
        const int M = batch * DIM;
        const int mmax = (M - m0 < MROWS) ? (M - m0) : MROWS;
        constexpr int W4 = MUL * DIM / 4;
        for (int idx = tid; idx < n_rows * W4; idx += 256) {
            const int zz = idx / W4;
            const int q  = idx - zz * W4;
            const int mlb = mbase + zz * DIM;
            float* op = out + (long)(z_lo + zz) * 592 + OFF + q * 4;
            if (mlb >= 0 && mlb + DIM <= mmax) {
                *(float4*)op = *(const float4*)&Dst2[zz * PD2 + q * 4];
            } else {
                #pragma unroll
                for (int e = 0; e < 4; ++e) {
                    const int cc = q * 4 + e;
                    const int i2 = cc % DIM;
                    const int ml = mlb + i2;
                    if (ml >= 0 && ml < mmax) op[e] = Dst2[zz * PD2 + cc];
                }
            }
        }
    }
}

__global__ void __launch_bounds__(256, 4) fused_irrep_kernel(
    const float* __restrict__ x, float* __restrict__ out, int batch,
    int nb0, int nb01, int nb012)
{
    extern __shared__ char smem[];
    const int b = blockIdx.x;
    if (b < nb0) {
        irrep_gemm<128, 1, 0, 0, 4, 2, 1>(x, out, batch, b, smem);
    } else if (b < nb01) {
        irrep_gemm<64, 3, 128, 20480, 8, 1, 1>(x, out, batch, b - nb0, smem);
    } else if (b < nb012) {
        irrep_gemm<32, 5, 320, 25600, 8, 1, 1>(x, out, batch, b - nb01, smem);
    } else {
        irrep_gemm<16, 7, 480, 26880, 8, 1, 2>(x, out, batch, b - nb012, smem);
    }
}

extern "C" void kernel_launch(void* const* d_in, const int* in_sizes, int n_in,
                              void* d_out, int out_size)
{
    const float* x = (const float*)d_in[0];
    const float* w = (const float*)d_in[1];
    float* out = (float*)d_out;
    const int batch = in_sizes[0] / 592;

    w_prep_kernel<<<(21760 + 255) / 256, 256>>>(w);

    const int nb0 = (batch + 63) / 64;          // MROWS 64
    const int nb1 = (batch * 3 + 127) / 128;    // MROWS 128
    const int nb2 = (batch * 5 + 127) / 128;    // MROWS 128
    const int nb3 = (batch * 7 + 255) / 256;    // MROWS 256
    const int total = nb0 + nb1 + nb2 + nb3;

    // max smem: block1 Dst2 = 44 rows * 196 floats * 4B = 34496
    const size_t smem = 34560;
    cudaFuncSetAttribute(fused_irrep_kernel,
                         cudaFuncAttributeMaxDynamicSharedMemorySize, (int)smem);
    fused_irrep_kernel<<<total, 256, smem>>>(x, out, batch,
                                             nb0, nb0 + nb1, nb0 + nb1 + nb2);
}